// round 14
// baseline (speedup 1.0000x reference)
#include <cuda_runtime.h>
#include <cuda_bf16.h>
#include <mma.h>
#include <cstdint>

using namespace nvcuda;

#define N_NODES 100000
#define N_EDGES 800000
#define F 128
#define C 64

#define TILE_M 128
#define N_TILES ((N_NODES + TILE_M - 1) / TILE_M)  // 782
#define N_PAD   (N_TILES * TILE_M)                 // 100096

#define SCAN_BLK 256
#define NBLK_SCAN ((N_NODES + SCAN_BLK - 1) / SCAN_BLK)  // 391

// Scratch (static device globals — no runtime allocation allowed)
__device__ float g_y[(size_t)N_PAD * C];    // y = x @ W^T (padded rows for ragged tile)
__device__ int   g_cnt[N_NODES];            // in-degree
__device__ int   g_start[N_NODES];          // CSR offsets (exclusive scan)
__device__ int   g_cursor[N_NODES];         // scatter cursors
__device__ int   g_elist[N_EDGES];          // CSR src lists
__device__ int   g_is64;                    // edge index dtype flag
__device__ int   g_ticket;                  // scan block ticket
__device__ unsigned int g_part[NBLK_SCAN];  // scan lookback words (flag|value)

#define SCAN_AGG    (1u << 30)
#define SCAN_PREFIX (1u << 31)
#define SCAN_MASK   0x3FFFFFFFu

// Smem tile layout for the wmma GEMM (bf16, padded leading dims)
#define LDA 136
#define LDB 136
#define A_BYTES (TILE_M * LDA * 2)          // 34816
#define B_BYTES (C * LDB * 2)               // 17408
#define OFF_AHI 0
#define OFF_ALO (A_BYTES)
#define OFF_BHI (2 * A_BYTES)
#define OFF_BLO (2 * A_BYTES + B_BYTES)
#define GEMM_SMEM (2 * A_BYTES + 2 * B_BYTES)  // 104448 bytes

// ---------------------------------------------------------------------------
// Probe: int64 vs int32 edge indices (parallel, warp-wide)
// ---------------------------------------------------------------------------
__global__ void detect_kernel(const unsigned int* __restrict__ p) {
    const int lid = threadIdx.x;
    unsigned int v = 0;
    for (int i = lid; i < 256; i += 32) v |= p[2 * i + 1];
    const unsigned int any = __ballot_sync(0xFFFFFFFFu, v != 0u);
    if (lid == 0) g_is64 = (any == 0u) ? 1 : 0;
}

__device__ __forceinline__ long long load_idx(const void* p, int e, int is64) {
    return is64 ? reinterpret_cast<const long long*>(p)[e]
                : (long long)reinterpret_cast<const int*>(p)[e];
}

// ---------------------------------------------------------------------------
// Kernel 1: y = x @ W^T via wmma bf16 with 3-product hi/lo split:
//   D = A_hi*B_hi + A_lo*B_hi + A_hi*B_lo  (fp32 accumulators)
// CTA: 256 threads (8 warps), tile M=128, N=64, K=128.
// Warp w computes rows [w*16, w*16+16). Also zeroes g_cnt.
// ---------------------------------------------------------------------------
__global__ void __launch_bounds__(256) gemm_wmma_kernel(const float* __restrict__ x,
                                                        const float* __restrict__ W) {
    extern __shared__ char smem[];
    __nv_bfloat16* Ahi = reinterpret_cast<__nv_bfloat16*>(smem + OFF_AHI);
    __nv_bfloat16* Alo = reinterpret_cast<__nv_bfloat16*>(smem + OFF_ALO);
    __nv_bfloat16* Bhi = reinterpret_cast<__nv_bfloat16*>(smem + OFF_BHI);
    __nv_bfloat16* Blo = reinterpret_cast<__nv_bfloat16*>(smem + OFF_BLO);

    const int tid  = threadIdx.x;
    const int wid  = tid >> 5;
    const int row0 = blockIdx.x * TILE_M;

    // ---- Load + convert A tile (x rows -> bf16 hi/lo), coalesced float4 ----
    {
        const float4* x4 = reinterpret_cast<const float4*>(x);
        for (int i = tid; i < (TILE_M * F) / 4; i += 256) {
            const int row = i >> 5;           // 32 float4 per row
            const int col = (i & 31) << 2;
            const int gr  = row0 + row;
            float4 v = (gr < N_NODES) ? x4[(size_t)gr * (F / 4) + (i & 31)]
                                      : make_float4(0.f, 0.f, 0.f, 0.f);
            __nv_bfloat16 h0 = __float2bfloat16(v.x);
            __nv_bfloat16 h1 = __float2bfloat16(v.y);
            __nv_bfloat16 h2 = __float2bfloat16(v.z);
            __nv_bfloat16 h3 = __float2bfloat16(v.w);
            __nv_bfloat16 l0 = __float2bfloat16(v.x - __bfloat162float(h0));
            __nv_bfloat16 l1 = __float2bfloat16(v.y - __bfloat162float(h1));
            __nv_bfloat16 l2 = __float2bfloat16(v.z - __bfloat162float(h2));
            __nv_bfloat16 l3 = __float2bfloat16(v.w - __bfloat162float(h3));
            __nv_bfloat162* hp =
                reinterpret_cast<__nv_bfloat162*>(Ahi + row * LDA + col);
            hp[0] = __nv_bfloat162(h0, h1);
            hp[1] = __nv_bfloat162(h2, h3);
            __nv_bfloat162* lp =
                reinterpret_cast<__nv_bfloat162*>(Alo + row * LDA + col);
            lp[0] = __nv_bfloat162(l0, l1);
            lp[1] = __nv_bfloat162(l2, l3);
        }
    }
    // ---- Load + convert B tile (W [c][k] -> bf16 hi/lo) ----
    {
        const float4* w4 = reinterpret_cast<const float4*>(W);
        for (int i = tid; i < (C * F) / 4; i += 256) {
            const int row = i >> 5;
            const int col = (i & 31) << 2;
            float4 v = w4[i];
            __nv_bfloat16 h0 = __float2bfloat16(v.x);
            __nv_bfloat16 h1 = __float2bfloat16(v.y);
            __nv_bfloat16 h2 = __float2bfloat16(v.z);
            __nv_bfloat16 h3 = __float2bfloat16(v.w);
            __nv_bfloat16 l0 = __float2bfloat16(v.x - __bfloat162float(h0));
            __nv_bfloat16 l1 = __float2bfloat16(v.y - __bfloat162float(h1));
            __nv_bfloat16 l2 = __float2bfloat16(v.z - __bfloat162float(h2));
            __nv_bfloat16 l3 = __float2bfloat16(v.w - __bfloat162float(h3));
            __nv_bfloat162* hp =
                reinterpret_cast<__nv_bfloat162*>(Bhi + row * LDB + col);
            hp[0] = __nv_bfloat162(h0, h1);
            hp[1] = __nv_bfloat162(h2, h3);
            __nv_bfloat162* lp =
                reinterpret_cast<__nv_bfloat162*>(Blo + row * LDB + col);
            lp[0] = __nv_bfloat162(l0, l1);
            lp[1] = __nv_bfloat162(l2, l3);
        }
    }
    // zero degree counters while we're here
    if (tid < TILE_M && row0 + tid < N_NODES) g_cnt[row0 + tid] = 0;
    __syncthreads();

    // ---- wmma mainloop: 3 products x 8 K-steps; warp owns 16 rows x 64 cols ----
    wmma::fragment<wmma::accumulator, 16, 16, 16, float> acc[4];
#pragma unroll
    for (int n = 0; n < 4; n++) wmma::fill_fragment(acc[n], 0.0f);

#pragma unroll
    for (int p = 0; p < 3; p++) {
        const __nv_bfloat16* Ap = (p == 1) ? Alo : Ahi;
        const __nv_bfloat16* Bp = (p == 2) ? Blo : Bhi;
#pragma unroll
        for (int k = 0; k < 8; k++) {
            wmma::fragment<wmma::matrix_a, 16, 16, 16, __nv_bfloat16,
                           wmma::row_major> fa;
            wmma::load_matrix_sync(fa, Ap + (wid * 16) * LDA + k * 16, LDA);
#pragma unroll
            for (int n = 0; n < 4; n++) {
                wmma::fragment<wmma::matrix_b, 16, 16, 16, __nv_bfloat16,
                               wmma::col_major> fb;
                // element (k', c') = Bp[(n*16+c')*LDB + k*16+k'] = W[c][k]
                wmma::load_matrix_sync(fb, Bp + (n * 16) * LDB + k * 16, LDB);
                wmma::mma_sync(acc[n], fa, fb, acc[n]);
            }
        }
    }

    // ---- Store: direct to g_y (padded, so ragged tail writes are safe) ----
    float* yb = g_y + (size_t)(row0 + wid * 16) * C;
#pragma unroll
    for (int n = 0; n < 4; n++)
        wmma::store_matrix_sync(yb + n * 16, acc[n], C, wmma::mem_row_major);
}

// ---------------------------------------------------------------------------
// Kernel 2: in-degree histogram (spread int atomics).
// Also resets the fused scan's ticket + lookback words (runs before scan).
// ---------------------------------------------------------------------------
__global__ void __launch_bounds__(256) hist_kernel(const void* __restrict__ dst_p) {
    const int e = blockIdx.x * blockDim.x + threadIdx.x;
    if (e < NBLK_SCAN) g_part[e] = 0u;
    if (e == 0) g_ticket = 0;
    if (e >= N_EDGES) return;
    const int d = (int)load_idx(dst_p, e, g_is64);
    atomicAdd(&g_cnt[d], 1);
}

// ---------------------------------------------------------------------------
// Kernel 3: fused exclusive scan of g_cnt -> g_start/g_cursor.
// Decoupled lookback, ticket-ordered blocks, single-word flag|value protocol
// (values <= 800000 fit in 30 bits, so the payload rides in the flag word).
// ---------------------------------------------------------------------------
__global__ void __launch_bounds__(SCAN_BLK) scan_fused_kernel() {
    __shared__ int sh[SCAN_BLK];
    __shared__ int s_bid;
    __shared__ int s_prefix;
    const int tid = threadIdx.x;

    if (tid == 0) s_bid = atomicAdd(&g_ticket, 1);
    __syncthreads();
    const int bid = s_bid;

    const int i = bid * SCAN_BLK + tid;
    const int v = (i < N_NODES) ? g_cnt[i] : 0;
    sh[tid] = v;
    __syncthreads();
#pragma unroll
    for (int off = 1; off < SCAN_BLK; off <<= 1) {
        int t = (tid >= off) ? sh[tid - off] : 0;
        __syncthreads();
        sh[tid] += t;
        __syncthreads();
    }
    const int incl = sh[tid];

    if (tid == 0) {
        const unsigned int total = (unsigned int)sh[SCAN_BLK - 1];
        if (bid == 0) {
            atomicExch(&g_part[0], total | SCAN_PREFIX);
            s_prefix = 0;
        } else {
            atomicExch(&g_part[bid], total | SCAN_AGG);
            unsigned int prefix = 0;
            int j = bid - 1;
            while (true) {
                unsigned int p = atomicAdd(&g_part[j], 0u);  // strong read
                if (p & SCAN_PREFIX) { prefix += p & SCAN_MASK; break; }
                if (p & SCAN_AGG)    { prefix += p & SCAN_MASK; j--; }
                // else: predecessor not published yet; spin
            }
            s_prefix = (int)prefix;
            atomicExch(&g_part[bid], (prefix + total) | SCAN_PREFIX);
        }
    }
    __syncthreads();

    if (i < N_NODES) {
        const int s = s_prefix + incl - v;   // global exclusive prefix
        g_start[i]  = s;
        g_cursor[i] = s;
    }
}

// ---------------------------------------------------------------------------
// Kernel 4: scatter src ids into CSR lists
// ---------------------------------------------------------------------------
__global__ void __launch_bounds__(256) scatter_kernel(const void* __restrict__ src_p,
                                                      const void* __restrict__ dst_p) {
    const int e = blockIdx.x * blockDim.x + threadIdx.x;
    if (e >= N_EDGES) return;
    const int is64 = g_is64;
    const int s = (int)load_idx(src_p, e, is64);
    const int d = (int)load_idx(dst_p, e, is64);
    const int pos = atomicAdd(&g_cursor[d], 1);
    g_elist[pos] = s;
}

// ---------------------------------------------------------------------------
// Kernel 5: gather + finalize. 16 lanes per dst node; lane owns one float4
// channel slice. out[v] = (y[v] + sum_u y[u]) / (deg+1) + b.
// ---------------------------------------------------------------------------
__global__ void __launch_bounds__(256) gather_kernel(const float* __restrict__ b,
                                                     float* __restrict__ out) {
    const int v    = blockIdx.x * (blockDim.x / 16) + (threadIdx.x >> 4);
    const int lane = threadIdx.x & 15;
    if (v >= N_NODES) return;

    const int start = g_start[v];
    const int cnt   = g_cnt[v];

    float4 acc = reinterpret_cast<const float4*>(g_y + (size_t)v * C)[lane];

    if (cnt > 0) {
        int s = g_elist[start];
        float4 u = reinterpret_cast<const float4*>(g_y + (size_t)s * C)[lane];
        for (int i = 1; i < cnt; i++) {
            int s_n = g_elist[start + i];
            float4 u_n = reinterpret_cast<const float4*>(g_y + (size_t)s_n * C)[lane];
            acc.x += u.x; acc.y += u.y; acc.z += u.z; acc.w += u.w;
            u = u_n;
        }
        acc.x += u.x; acc.y += u.y; acc.z += u.z; acc.w += u.w;
    }

    const float inv = 1.0f / (float)(cnt + 1);
    const float4 bv = reinterpret_cast<const float4*>(b)[lane];
    float4 o;
    o.x = acc.x * inv + bv.x;
    o.y = acc.y * inv + bv.y;
    o.z = acc.z * inv + bv.z;
    o.w = acc.w * inv + bv.w;
    reinterpret_cast<float4*>(out)[(size_t)v * (C / 4) + lane] = o;
}

// ---------------------------------------------------------------------------
// Launcher. Inputs (metadata order): x, edge_src, edge_dst, W_neigh, b_neigh.
// ---------------------------------------------------------------------------
extern "C" void kernel_launch(void* const* d_in, const int* in_sizes, int n_in,
                              void* d_out, int out_size) {
    const float* x   = (const float*)d_in[0];
    const void*  es  = d_in[1];
    const void*  ed  = d_in[2];
    const float* W   = (const float*)d_in[3];
    const float* b   = (const float*)d_in[4];
    float*       out = (float*)d_out;

    cudaFuncSetAttribute(gemm_wmma_kernel,
                         cudaFuncAttributeMaxDynamicSharedMemorySize, GEMM_SMEM);

    detect_kernel<<<1, 32>>>((const unsigned int*)es);

    gemm_wmma_kernel<<<N_TILES, 256, GEMM_SMEM>>>(x, W);

    hist_kernel<<<(N_EDGES + 255) / 256, 256>>>(ed);

    scan_fused_kernel<<<NBLK_SCAN, SCAN_BLK>>>();

    scatter_kernel<<<(N_EDGES + 255) / 256, 256>>>(es, ed);

    gather_kernel<<<(N_NODES * 16 + 255) / 256, 256>>>(b, out);
}